// round 16
// baseline (speedup 1.0000x reference)
#include <cuda_runtime.h>
#include <cuda_fp16.h>

// Cubic B-spline prefilter (Unser), DCT-II mirror boundaries.
// kWH: W and H axes via the EXACT causal/anticausal IIR (pole p = sqrt(3)-2),
//      block-parallel with 12-step warm-up (error ~p^12 ~ 1e-7).
//      Output staged as fp16 in g_mid.
// kD : D axis as truncated 13-tap FIR (radius 6), fp16 -> f32, unchanged.

#define NAX   192
#define KR    6
#define NT    (2*KR + 1)        // 13 taps (kD only)
#define HALO2 12                // IIR warm-up length
#define TW    32                // strip output width
#define LC    (TW + 2*HALO2)    // 56 loaded cols
#define P1    57                // smem pitch (odd -> conflict-free both ways)
#define SEGD  24
#define WLD   (SEGD + 2*KR)     // 36
#define TPBF  192
#define TPBD  256
#define VOL   (NAX * NAX * NAX)
#define NCH   8                 // 4 batch * 2 channel

#define PZ      (-0.26794919243112270647f)  // p = sqrt(3) - 2
#define INV1MP  (0.78867513459481287f)      // 1 / (1 - p)
#define PDIV    (0.21132486540518713f)      // p / (p - 1)

// fp16 staging buffer for the W+H intermediate (113 MB; legal scratch)
__device__ __half g_mid[(size_t)NCH * VOL];

// kD taps T[k] = sqrt(3)*p^|k-6| -> FFMA-imm in SASS (rt=1)
#define DECL_TAPS const float T[NT] = { \
     6.4102556e-04f, -2.3923386e-03f,  8.9283341e-03f, -3.3320997e-02f, \
     1.2435565e-01f, -4.6410161e-01f,  1.7320508e+00f, -4.6410161e-01f, \
     1.2435565e-01f, -3.3320997e-02f,  8.9283341e-03f, -2.3923386e-03f, \
     6.4102556e-04f }

__device__ __forceinline__ int mirror_idx(int i) {
    i = (i < 0) ? (-1 - i) : i;                  // half-sample left reflect
    return (i >= NAX) ? (2 * NAX - 1 - i) : i;   // half-sample right reflect
}

// ---------------------------------------------------------------------------
// Fused W+H pass (IIR), one 192 x 32 strip per block, one 192x57 smem buffer.
// ---------------------------------------------------------------------------
__global__ __launch_bounds__(TPBF, 5) void kWH(const float* __restrict__ in) {
    extern __shared__ float s[];   // [192][P1]

    const int tid   = threadIdx.x;              // 0..191
    const int strip = blockIdx.x % (NAX / TW);  // 6 strips
    const int slice = blockIdx.x / (NAX / TW);
    const int base  = slice * (NAX * NAX);
    const int wbase = strip * TW;

    // ---- load 192 x 56 (mirrored halo of 12; coalesced independent LDG)
#pragma unroll
    for (int k = 0; k < (NAX * LC) / TPBF; ++k) {   // 56 iterations
        int i   = tid + TPBF * k;
        int row = i / LC;
        int c   = i - row * LC;
        s[row * P1 + c] = in[base + row * NAX + mirror_idx(wbase - HALO2 + c)];
    }
    __syncthreads();

    // ==== W axis IIR: thread owns row `tid` (private smem span -> no races)
    {
        float* rp = &s[tid * P1];   // stride-57 -> conflict-free
        // causal u[i] = x[i] + p*u[i-1], steady-state init, 12-step warm-up
        float u = rp[0] * INV1MP;
#pragma unroll
        for (int i = 1; i < HALO2; ++i) u = fmaf(PZ, u, rp[i]);
#pragma unroll
        for (int i = HALO2; i < LC; ++i) { u = fmaf(PZ, u, rp[i]); rp[i] = u; }

        // anticausal v[i] = p*(v[i+1] - u[i]); write 6*v in place
        float v;
        if (strip == (NAX / TW - 1)) {
            v = rp[HALO2 + TW - 1] * PDIV;       // exact boundary init at x=191
            rp[HALO2 + TW - 1] = 6.0f * v;
        } else {
            v = rp[LC - 1] * PDIV;               // steady-state init + warm-up
#pragma unroll
            for (int i = LC - 2; i >= HALO2 + TW; --i) v = PZ * (v - rp[i]);
            v = PZ * (v - rp[HALO2 + TW - 1]);
            rp[HALO2 + TW - 1] = 6.0f * v;
        }
#pragma unroll
        for (int i = HALO2 + TW - 2; i >= HALO2; --i) {
            v = PZ * (v - rp[i]);
            rp[i] = 6.0f * v;
        }
    }
    __syncthreads();

    // ==== H axis IIR: 192 tasks = (w 0..31) x (seg 0..5 of 32 rows)
    const int w    = tid & 31;
    const int g    = tid >> 5;                  // 0..5
    const int colw = HALO2 + w;
    const int s0   = 32 * g;

    // H1: causal into registers (reads only -> no races)
    float u;
    {
        u = s[mirror_idx(s0 - HALO2) * P1 + colw] * INV1MP;
#pragma unroll
        for (int m = 1; m < HALO2; ++m)
            u = fmaf(PZ, u, s[mirror_idx(s0 - HALO2 + m) * P1 + colw]);
    }
    float ur[TW];
#pragma unroll
    for (int j = 0; j < TW; ++j) {
        u = fmaf(PZ, u, s[(s0 + j) * P1 + colw]);
        ur[j] = u;
    }
    __syncthreads();

    // H2: publish u for the neighbor's anticausal warm-up
#pragma unroll
    for (int j = 0; j < TW; ++j) s[(s0 + j) * P1 + colw] = ur[j];
    __syncthreads();

    // H3: anticausal; direct fp16 STG (no smem writeback)
    float v;
    if (g == 5) {
        v = ur[TW - 1] * PDIV;                  // exact boundary init at h=191
    } else {
        v = s[(s0 + 32 + 11) * P1 + colw] * PDIV;   // neighbor u, warm-up 12
#pragma unroll
        for (int m = 10; m >= 0; --m) v = PZ * (v - s[(s0 + 32 + m) * P1 + colw]);
        v = PZ * (v - ur[TW - 1]);
    }
    __half* o = g_mid + base + wbase + w;
    o[(s0 + TW - 1) * NAX] = __float2half_rn(6.0f * v);
#pragma unroll
    for (int j = TW - 2; j >= 0; --j) {
        v = PZ * (v - ur[j]);
        o[(s0 + j) * NAX] = __float2half_rn(6.0f * v);   // 64B coalesced per j
    }
}

// ---------------------------------------------------------------------------
// D pass (stride 192*192): g_mid (fp16) -> out (f32). Tile: 192(d) x 32(w).
// Occupancy 6 (regs 40 <= cap 42).  (R15, unchanged)
// ---------------------------------------------------------------------------
__global__ __launch_bounds__(TPBD, 6) void kD(float* __restrict__ out) {
    __shared__ float s[NAX][32];
    const int tid = threadIdx.x;
    const int c   = blockIdx.x % (NAX / 32);
    const int tt  = blockIdx.x / (NAX / 32);
    const int b   = tt / NAX;
    const int hh  = tt % NAX;
    const int base = b * VOL + hh * NAX + c * 32;

    const int w  = tid & 31;
    const int a4 = tid >> 5;
    const __half* src = g_mid + base + w;
#pragma unroll
    for (int k = 0; k < NAX / 8; ++k)   // 24 outstanding LDG.16/thread
        s[a4 + 8 * k][w] = __half2float(src[(a4 + 8 * k) * (NAX * NAX)]);
    __syncthreads();

    DECL_TAPS;
    const int a0 = (tid >> 5) * SEGD;
    float win[WLD];
#pragma unroll
    for (int m = 0; m < WLD; ++m)
        win[m] = s[mirror_idx(a0 - KR + m)][w];

#pragma unroll
    for (int j = 0; j < SEGD; ++j) {
        float acc = 0.0f;
#pragma unroll
        for (int k = 0; k < NT; ++k) acc = fmaf(T[k], win[j + k], acc);
        out[base + (a0 + j) * (NAX * NAX) + w] = acc;     // 128B coalesced per j
    }
}

extern "C" void kernel_launch(void* const* d_in, const int* in_sizes, int n_in,
                              void* d_out, int out_size) {
    const float* x = (const float*)d_in[0];
    float* y = (float*)d_out;

    const int smemWH = NAX * P1 * (int)sizeof(float);   // 43776 B

    static int attr_set = 0;
    if (!attr_set) {
        cudaFuncSetAttribute(kWH, cudaFuncAttributeMaxDynamicSharedMemorySize, smemWH);
        attr_set = 1;
    }

    const int gridWH = NCH * NAX * (NAX / TW);   // 9216 blocks
    const int gridD  = NCH * NAX * (NAX / 32);   // 9216 blocks

    kWH<<<gridWH, TPBF, smemWH>>>(x);   // W+H IIR: x -> g_mid (fp16)
    kD<<<gridD, TPBD>>>(y);             // D FIR: g_mid -> d_out (f32)
}